// round 2
// baseline (speedup 1.0000x reference)
#include <cuda_runtime.h>
#include <cuda_bf16.h>

// WTA2D: per (B,C) row of H*W=3136 fp32, t = 313th-largest, out = (t > x) ? x : 0.
//
// One CTA (256 thr) per row, row in registers (16 keys/thread).
// Round 1: 16-bucket packed-nibble histogram over registers (block reduce).
// Compact the selected bucket to shared (per-thread counts extracted FREE from
// the packed histogram), then warp 0 alone runs the remaining nibble rounds on
// the shrinking candidate list (in-place compaction), finishing with ballot
// bisection. Other warps' issue slots stay free for co-resident CTAs.

#define NROW 3136
#define KSEL 313u

__device__ __forceinline__ unsigned f2k(float f) {
    unsigned u = __float_as_uint(f);
    return (u & 0x80000000u) ? ~u : (u | 0x80000000u);
}
__device__ __forceinline__ float k2f(unsigned k) {
    unsigned u = (k & 0x80000000u) ? (k ^ 0x80000000u) : ~k;
    return __uint_as_float(u);
}

__global__ void __launch_bounds__(256)
wta2d_kernel(const float* __restrict__ x, float* __restrict__ out) {
    const int tid  = threadIdx.x;
    const int lane = tid & 31;
    const int warp = tid >> 5;
    const size_t base = (size_t)blockIdx.x * NROW;

    __shared__ unsigned buf[NROW + 32];     // candidate keys
    __shared__ uint4 wsum[8][4];            // round-1 per-warp byte-packed counts
    __shared__ unsigned warpcnt[8];         // compaction warp totals
    __shared__ unsigned sb_d1, sb_rank, sb_m, sb_tkey;

    // ---- load row -> keys in registers ----
    unsigned key[16];
    const bool has4 = (tid < 16);
    const float4* xin = reinterpret_cast<const float4*>(x + base);
#pragma unroll
    for (int s = 0; s < 4; ++s) {
        int p = tid + s * 256;
        if (s < 3 || has4) {
            float4 f = xin[p];
            key[4*s+0] = f2k(f.x); key[4*s+1] = f2k(f.y);
            key[4*s+2] = f2k(f.z); key[4*s+3] = f2k(f.w);
        } else {
            key[4*s+0] = key[4*s+1] = key[4*s+2] = key[4*s+3] = 0u;
        }
    }

    // ---- round 1: 16-bucket histogram of top nibble, packed 4-bit fields ----
    unsigned long long acc0 = 0ull, acc1 = 0ull;   // j<8 / j>=8 (fields <= 8)
#pragma unroll
    for (int j = 0; j < 16; ++j) {
        unsigned s = (key[j] >> 26) & 0x3Cu;       // 4 * top_nibble
        unsigned long long inc = 1ull << s;
        bool valid = (j < 12) || has4;
        if (j < 8) acc0 += inc;
        else if (valid) acc1 += inc;
    }
    {   // expand nibbles->bytes, 8-lane reduce, stage per warp
        unsigned lo0 = (unsigned)acc0, hi0 = (unsigned)(acc0 >> 32);
        unsigned lo1 = (unsigned)acc1, hi1 = (unsigned)(acc1 >> 32);
        unsigned r0 = (lo0 & 0x0F0F0F0Fu)        + (lo1 & 0x0F0F0F0Fu);
        unsigned r1 = ((lo0 >> 4) & 0x0F0F0F0Fu) + ((lo1 >> 4) & 0x0F0F0F0Fu);
        unsigned r2 = (hi0 & 0x0F0F0F0Fu)        + (hi1 & 0x0F0F0F0Fu);
        unsigned r3 = ((hi0 >> 4) & 0x0F0F0F0Fu) + ((hi1 >> 4) & 0x0F0F0F0Fu);
#pragma unroll
        for (int off = 1; off <= 4; off <<= 1) {
            r0 += __shfl_xor_sync(0xFFFFFFFFu, r0, off);
            r1 += __shfl_xor_sync(0xFFFFFFFFu, r1, off);
            r2 += __shfl_xor_sync(0xFFFFFFFFu, r2, off);
            r3 += __shfl_xor_sync(0xFFFFFFFFu, r3, off);
        }
        if ((lane & 7) == 0) wsum[warp][lane >> 3] = make_uint4(r0, r1, r2, r3);
    }
    __syncthreads();

    if (warp == 0) {        // combine, suffix-scan, pick bucket
        unsigned cnt = 0;
        if (lane < 16) {
            int word = (lane & 1) | ((lane >> 3) << 1);
            int sh   = ((lane & 7) >> 1) * 8;
#pragma unroll
            for (int w = 0; w < 8; ++w)
#pragma unroll
                for (int g = 0; g < 4; ++g) {
                    const unsigned* ws = reinterpret_cast<const unsigned*>(&wsum[w][g]);
                    cnt += (ws[word] >> sh) & 0xFFu;
                }
        }
        unsigned ssum = cnt;
#pragma unroll
        for (int off = 1; off <= 8; off <<= 1) {
            unsigned v = __shfl_down_sync(0xFFFFFFFFu, ssum, off);
            if (lane + off < 16) ssum += v;
        }
        if (lane < 16 && ssum >= KSEL && (ssum - cnt) < KSEL) {
            sb_d1   = (unsigned)lane;
            sb_rank = KSEL - (ssum - cnt);
            sb_m    = cnt;
        }
    }
    __syncthreads();
    const unsigned d1 = sb_d1;

    // ---- compact selected bucket to shared; per-thread count is FREE ----
    unsigned mycnt = ((unsigned)(acc0 >> (d1 * 4)) & 15u)
                   + ((unsigned)(acc1 >> (d1 * 4)) & 15u);
    unsigned isum = mycnt;
#pragma unroll
    for (int off = 1; off <= 16; off <<= 1) {
        unsigned v = __shfl_up_sync(0xFFFFFFFFu, isum, off);
        if (lane >= off) isum += v;
    }
    if (lane == 31) warpcnt[warp] = isum;
    __syncthreads();
    unsigned pos = isum - mycnt;
#pragma unroll
    for (int w = 0; w < 8; ++w) pos += (w < warp) ? warpcnt[w] : 0u;
#pragma unroll
    for (int j = 0; j < 16; ++j) {
        bool valid = (j < 12) || has4;
        if (valid && ((key[j] >> 28) == d1)) buf[pos++] = key[j];
    }
    __syncthreads();

    // ---- warp 0: nibble rounds on shrinking list, then bit bisection ----
    if (warp == 0) {
        unsigned mm = sb_m, rk = sb_rank, prefix = d1;
        int shift = 24;
        while (mm > 32 && shift >= 0) {
            // count nibbles (byte-packed: fields <= ceil(3136/32)=98)
            unsigned long long a0 = 0ull, a1 = 0ull;
            for (unsigned i = lane; i < mm; i += 32) {
                unsigned k = buf[i];
                unsigned d = (k >> shift) & 15u;
                unsigned long long inc = 1ull << ((d & 7u) * 8u);
                if (d < 8u) a0 += inc; else a1 += inc;
            }
            a0 += __shfl_xor_sync(0xFFFFFFFFu, a0, 1);   // <=196, byte-safe
            a1 += __shfl_xor_sync(0xFFFFFFFFu, a1, 1);
            unsigned long long e0 =  a0       & 0x00FF00FF00FF00FFull; // b 0,2,4,6
            unsigned long long e1 = (a0 >> 8) & 0x00FF00FF00FF00FFull; // b 1,3,5,7
            unsigned long long e2 =  a1       & 0x00FF00FF00FF00FFull; // b 8,10,12,14
            unsigned long long e3 = (a1 >> 8) & 0x00FF00FF00FF00FFull; // b 9,11,13,15
#pragma unroll
            for (int off = 2; off <= 16; off <<= 1) {
                e0 += __shfl_xor_sync(0xFFFFFFFFu, e0, off);
                e1 += __shfl_xor_sync(0xFFFFFFFFu, e1, off);
                e2 += __shfl_xor_sync(0xFFFFFFFFu, e2, off);
                e3 += __shfl_xor_sync(0xFFFFFFFFu, e3, off);
            }
            unsigned cnt = 0;
            if (lane < 16) {
                unsigned long long src = (lane < 8) ? ((lane & 1) ? e1 : e0)
                                                    : ((lane & 1) ? e3 : e2);
                cnt = (unsigned)(src >> (((lane >> 1) & 3) * 16)) & 0xFFFFu;
            }
            unsigned ssum = cnt;
#pragma unroll
            for (int off = 1; off <= 8; off <<= 1) {
                unsigned v = __shfl_down_sync(0xFFFFFFFFu, ssum, off);
                if (lane + off < 16) ssum += v;
            }
            bool cross = (lane < 16) && (ssum >= rk) && ((ssum - cnt) < rk);
            unsigned cl = __ffs(__ballot_sync(0xFFFFFFFFu, cross)) - 1u;
            unsigned above = __shfl_sync(0xFFFFFFFFu, ssum - cnt, cl);
            unsigned nm    = __shfl_sync(0xFFFFFFFFu, cnt, cl);
            rk -= above;
            prefix = (prefix << 4) | cl;
            // in-place compact (single warp: batch reads complete before writes)
            unsigned wb = 0;
            for (unsigned bb = 0; bb < mm; bb += 32) {
                unsigned i = bb + lane;
                bool v = i < mm;
                unsigned k = v ? buf[i] : 0u;
                bool match = v && (((k >> shift) & 15u) == cl);
                unsigned bal = __ballot_sync(0xFFFFFFFFu, match);
                unsigned p = wb + __popc(bal & ((1u << lane) - 1u));
                if (match) buf[p] = k;
                wb += __popc(bal);
            }
            mm = nm;
            shift -= 4;
        }
        // tail
        unsigned tk;
        int rem = shift + 4;
        if (rem <= 0) {
            tk = prefix;                         // all 32 bits resolved
        } else {
            unsigned ck = (lane < (int)mm) ? buf[lane] : 0u;
            bool alive = (lane < (int)mm);
            unsigned r = rk;
            tk = prefix << rem;
            for (int b = rem - 1; b >= 0; --b) {
                bool bit = ((ck >> b) & 1u) != 0u;
                unsigned bal = __ballot_sync(0xFFFFFFFFu, alive && bit);
                unsigned c = __popc(bal);
                if (c >= r) { alive = alive && bit; tk |= (1u << b); }
                else        { r -= c; alive = alive && !bit; }
            }
        }
        if (lane == 0) sb_tkey = tk;
    }
    __syncthreads();
    const unsigned tkey = sb_tkey;

    // ---- mask + store (key < tkey  <=>  x < t) ----
    float4* po = reinterpret_cast<float4*>(out + base);
#pragma unroll
    for (int s = 0; s < 4; ++s) {
        int p = tid + s * 256;
        if (s < 3 || has4) {
            float4 o;
            o.x = (key[4*s+0] < tkey) ? k2f(key[4*s+0]) : 0.0f;
            o.y = (key[4*s+1] < tkey) ? k2f(key[4*s+1]) : 0.0f;
            o.z = (key[4*s+2] < tkey) ? k2f(key[4*s+2]) : 0.0f;
            o.w = (key[4*s+3] < tkey) ? k2f(key[4*s+3]) : 0.0f;
            po[p] = o;
        }
    }
}

extern "C" void kernel_launch(void* const* d_in, const int* in_sizes, int n_in,
                              void* d_out, int out_size) {
    const float* x = (const float*)d_in[0];
    float* out = (float*)d_out;
    int rows = in_sizes[0] / NROW;   // 16384
    wta2d_kernel<<<rows, 256>>>(x, out);
}

// round 3
// speedup vs baseline: 1.9539x; 1.9539x over previous
#include <cuda_runtime.h>
#include <cuda_bf16.h>

// WTA2D: per (B,C) row of H*W=3136 fp32, t = 313th-largest, out = (t > x) ? x : 0.
//
// One CTA (256 thr) per row, row in registers (16 keys/thread).
// Round 1: 16-bucket packed-nibble histogram over registers (all warps).
// Compact the selected bucket to shared ONCE (per-thread counts free from the
// packed histogram). Rounds 2..4 run over the static compacted list with ALL
// 256 threads (~6 elems/thread). Tail: gather <=32 candidates, warp-0 ballot
// bisection. No serial long phase, no recompaction.

#define NROW 3136
#define KSEL 313u

__device__ __forceinline__ unsigned f2k(float f) {
    unsigned u = __float_as_uint(f);
    return (u & 0x80000000u) ? ~u : (u | 0x80000000u);
}
__device__ __forceinline__ float k2f(unsigned k) {
    unsigned u = (k & 0x80000000u) ? (k ^ 0x80000000u) : ~k;
    return __uint_as_float(u);
}

__global__ void __launch_bounds__(256)
wta2d_kernel(const float* __restrict__ x, float* __restrict__ out) {
    const int tid  = threadIdx.x;
    const int lane = tid & 31;
    const int warp = tid >> 5;
    const size_t base = (size_t)blockIdx.x * NROW;

    __shared__ unsigned buf[NROW];          // compacted candidate keys
    __shared__ uint4 wsum[8][4];            // per-warp byte-packed 16-bucket counts
    __shared__ unsigned warpcnt[8];
    __shared__ unsigned sb_prefix, sb_rank, sb_m, sb_tkey;
    __shared__ unsigned gbuf[32];
    __shared__ int gcount;

    // ---- load row -> keys in registers ----
    unsigned key[16];
    const bool has4 = (tid < 16);
    const float4* xin = reinterpret_cast<const float4*>(x + base);
#pragma unroll
    for (int s = 0; s < 4; ++s) {
        int p = tid + s * 256;
        if (s < 3 || has4) {
            float4 f = xin[p];
            key[4*s+0] = f2k(f.x); key[4*s+1] = f2k(f.y);
            key[4*s+2] = f2k(f.z); key[4*s+3] = f2k(f.w);
        } else {
            key[4*s+0] = key[4*s+1] = key[4*s+2] = key[4*s+3] = 0u;
        }
    }

    // ---- round 1: top-nibble histogram, nibble-packed (two accs, fields <= 8) ----
    unsigned long long acc0 = 0ull, acc1 = 0ull;
#pragma unroll
    for (int j = 0; j < 16; ++j) {
        unsigned s = (key[j] >> 26) & 0x3Cu;   // 4 * top_nibble
        unsigned long long inc = 1ull << s;
        bool valid = (j < 12) || has4;
        if (j < 8) acc0 += inc;
        else if (valid) acc1 += inc;
    }
    {
        unsigned lo0 = (unsigned)acc0, hi0 = (unsigned)(acc0 >> 32);
        unsigned lo1 = (unsigned)acc1, hi1 = (unsigned)(acc1 >> 32);
        unsigned r0 = (lo0 & 0x0F0F0F0Fu)        + (lo1 & 0x0F0F0F0Fu);
        unsigned r1 = ((lo0 >> 4) & 0x0F0F0F0Fu) + ((lo1 >> 4) & 0x0F0F0F0Fu);
        unsigned r2 = (hi0 & 0x0F0F0F0Fu)        + (hi1 & 0x0F0F0F0Fu);
        unsigned r3 = ((hi0 >> 4) & 0x0F0F0F0Fu) + ((hi1 >> 4) & 0x0F0F0F0Fu);
#pragma unroll
        for (int off = 1; off <= 4; off <<= 1) {
            r0 += __shfl_xor_sync(0xFFFFFFFFu, r0, off);
            r1 += __shfl_xor_sync(0xFFFFFFFFu, r1, off);
            r2 += __shfl_xor_sync(0xFFFFFFFFu, r2, off);
            r3 += __shfl_xor_sync(0xFFFFFFFFu, r3, off);
        }
        if ((lane & 7) == 0) wsum[warp][lane >> 3] = make_uint4(r0, r1, r2, r3);
    }
    __syncthreads();

    if (warp == 0) {    // combine, suffix-scan, pick bucket
        unsigned cnt = 0;
        if (lane < 16) {
            int word = (lane & 1) | ((lane >> 3) << 1);
            int sh   = ((lane & 7) >> 1) * 8;
#pragma unroll
            for (int w = 0; w < 8; ++w)
#pragma unroll
                for (int g = 0; g < 4; ++g) {
                    const unsigned* ws = reinterpret_cast<const unsigned*>(&wsum[w][g]);
                    cnt += (ws[word] >> sh) & 0xFFu;
                }
        }
        unsigned ssum = cnt;
#pragma unroll
        for (int off = 1; off <= 8; off <<= 1) {
            unsigned v = __shfl_down_sync(0xFFFFFFFFu, ssum, off);
            if (lane + off < 16) ssum += v;
        }
        if (lane < 16 && ssum >= KSEL && (ssum - cnt) < KSEL) {
            sb_prefix = (unsigned)lane;
            sb_rank   = KSEL - (ssum - cnt);
            sb_m      = cnt;
        }
    }
    __syncthreads();
    const unsigned d1 = sb_prefix;
    const unsigned m1 = sb_m;              // fixed length of compacted list

    // ---- compact bucket d1 to shared (per-thread count free from packed accs) ----
    unsigned mycnt = ((unsigned)(acc0 >> (d1 * 4)) & 15u)
                   + ((unsigned)(acc1 >> (d1 * 4)) & 15u);
    unsigned isum = mycnt;
#pragma unroll
    for (int off = 1; off <= 16; off <<= 1) {
        unsigned v = __shfl_up_sync(0xFFFFFFFFu, isum, off);
        if (lane >= off) isum += v;
    }
    if (lane == 31) warpcnt[warp] = isum;
    __syncthreads();
    unsigned pos = isum - mycnt;
#pragma unroll
    for (int w = 0; w < 8; ++w) pos += (w < warp) ? warpcnt[w] : 0u;
#pragma unroll
    for (int j = 0; j < 16; ++j) {
        bool valid = (j < 12) || has4;
        if (valid && ((key[j] >> 28) == d1)) buf[pos++] = key[j];
    }
    __syncthreads();

    // ---- rounds 2..4: all threads scan the static list ----
    unsigned prefix = d1, rk = sb_rank, mcur = m1;
    int shift = 24;
    while (mcur > 32 && shift >= 0) {
        unsigned long long acc = 0ull;     // 16 nibble fields, per-thread elems <= 13
        int top = shift + 4;
        for (unsigned i = tid; i < m1; i += 256) {
            unsigned k = buf[i];
            bool match = ((k >> top) == prefix);   // round 2: always true
            unsigned s = ((k >> shift) & 15u) * 4u;
            if (match) acc += 1ull << s;
        }
        {
            unsigned lo = (unsigned)acc, hi = (unsigned)(acc >> 32);
            unsigned r0 = (lo & 0x0F0F0F0Fu);
            unsigned r1 = ((lo >> 4) & 0x0F0F0F0Fu);
            unsigned r2 = (hi & 0x0F0F0F0Fu);
            unsigned r3 = ((hi >> 4) & 0x0F0F0F0Fu);
#pragma unroll
            for (int off = 1; off <= 4; off <<= 1) {
                r0 += __shfl_xor_sync(0xFFFFFFFFu, r0, off);
                r1 += __shfl_xor_sync(0xFFFFFFFFu, r1, off);
                r2 += __shfl_xor_sync(0xFFFFFFFFu, r2, off);
                r3 += __shfl_xor_sync(0xFFFFFFFFu, r3, off);
            }
            if ((lane & 7) == 0) wsum[warp][lane >> 3] = make_uint4(r0, r1, r2, r3);
        }
        __syncthreads();
        if (warp == 0) {
            unsigned cnt = 0;
            if (lane < 16) {
                int word = (lane & 1) | ((lane >> 3) << 1);
                int sh   = ((lane & 7) >> 1) * 8;
#pragma unroll
                for (int w = 0; w < 8; ++w)
#pragma unroll
                    for (int g = 0; g < 4; ++g) {
                        const unsigned* ws = reinterpret_cast<const unsigned*>(&wsum[w][g]);
                        cnt += (ws[word] >> sh) & 0xFFu;
                    }
            }
            unsigned ssum = cnt;
#pragma unroll
            for (int off = 1; off <= 8; off <<= 1) {
                unsigned v = __shfl_down_sync(0xFFFFFFFFu, ssum, off);
                if (lane + off < 16) ssum += v;
            }
            if (lane < 16 && ssum >= rk && (ssum - cnt) < rk) {
                sb_prefix = (prefix << 4) | (unsigned)lane;
                sb_rank   = rk - (ssum - cnt);
                sb_m      = cnt;
            }
        }
        __syncthreads();
        prefix = sb_prefix; rk = sb_rank; mcur = sb_m;
        shift -= 4;
    }

    // ---- tail: gather <=32 candidates, warp-0 ballot bisection ----
    int rem = shift + 4;
    if (rem > 0) {
        if (tid == 0) gcount = 0;
        __syncthreads();
        for (unsigned i = tid; i < m1; i += 256) {
            unsigned k = buf[i];
            if ((k >> rem) == prefix) {
                int p = atomicAdd(&gcount, 1);
                if (p < 32) gbuf[p] = k;
            }
        }
        __syncthreads();
        if (warp == 0) {
            int n = gcount; if (n > 32) n = 32;
            unsigned ck = (lane < n) ? gbuf[lane] : 0u;
            bool alive = (lane < n);
            unsigned r = rk;
            unsigned tk = prefix << rem;
            for (int b = rem - 1; b >= 0; --b) {
                bool bit = ((ck >> b) & 1u) != 0u;
                unsigned bal = __ballot_sync(0xFFFFFFFFu, alive && bit);
                unsigned c = __popc(bal);
                if (c >= r) { alive = alive && bit; tk |= (1u << b); }
                else        { r -= c; alive = alive && !bit; }
            }
            if (lane == 0) sb_tkey = tk;
        }
    } else {
        if (tid == 0) sb_tkey = prefix;    // all 32 bits resolved (ties)
    }
    __syncthreads();
    const unsigned tkey = sb_tkey;

    // ---- mask + store (key < tkey  <=>  x < t) ----
    float4* po = reinterpret_cast<float4*>(out + base);
#pragma unroll
    for (int s = 0; s < 4; ++s) {
        int p = tid + s * 256;
        if (s < 3 || has4) {
            float4 o;
            o.x = (key[4*s+0] < tkey) ? k2f(key[4*s+0]) : 0.0f;
            o.y = (key[4*s+1] < tkey) ? k2f(key[4*s+1]) : 0.0f;
            o.z = (key[4*s+2] < tkey) ? k2f(key[4*s+2]) : 0.0f;
            o.w = (key[4*s+3] < tkey) ? k2f(key[4*s+3]) : 0.0f;
            po[p] = o;
        }
    }
}

extern "C" void kernel_launch(void* const* d_in, const int* in_sizes, int n_in,
                              void* d_out, int out_size) {
    const float* x = (const float*)d_in[0];
    float* out = (float*)d_out;
    int rows = in_sizes[0] / NROW;   // 16384
    wta2d_kernel<<<rows, 256>>>(x, out);
}

// round 4
// speedup vs baseline: 2.0953x; 1.0724x over previous
#include <cuda_runtime.h>
#include <cuda_bf16.h>

// WTA2D: per (B,C) row of H*W=3136 fp32, t = 313th-largest, out = (t > x) ? x : 0.
//
// One CTA (256 thr) per row, row in registers (16 keys/thread).
// Round 1: 12-bit digit (4096-bucket shared ATOMIC histogram) -> selected bucket
// typically ~60-110 elems. Pick via two-pass LDS walk + block suffix-scan.
// Compact bucket to shared once. Then at most 1-2 cheap 4-bit rounds (all
// threads) over the tiny static list, tail gather + warp-0 ballot bisection.

#define NROW 3136
#define KSEL 313u

__device__ __forceinline__ unsigned f2k(float f) {
    unsigned u = __float_as_uint(f);
    return (u & 0x80000000u) ? ~u : (u | 0x80000000u);
}
__device__ __forceinline__ float k2f(unsigned k) {
    unsigned u = (k & 0x80000000u) ? (k ^ 0x80000000u) : ~k;
    return __uint_as_float(u);
}

__global__ void __launch_bounds__(256)
wta2d_kernel(const float* __restrict__ x, float* __restrict__ out) {
    const int tid  = threadIdx.x;
    const int lane = tid & 31;
    const int warp = tid >> 5;
    const size_t base = (size_t)blockIdx.x * NROW;

    __shared__ unsigned hist[4096];        // 16KB: 12-bit digit histogram
    __shared__ unsigned buf[NROW];         // compacted candidate keys
    __shared__ uint4 wsum[8][4];           // per-warp packed counts (4-bit rounds)
    __shared__ unsigned warpcnt[8];
    __shared__ unsigned sb_d1, sb_rank, sb_m, sb_tkey;
    __shared__ unsigned gbuf[32];
    __shared__ int gcount;

    // ---- zero histogram (vectorized) ----
    {
        uint4 z = make_uint4(0u, 0u, 0u, 0u);
        uint4* h4 = reinterpret_cast<uint4*>(hist);
#pragma unroll
        for (int i = 0; i < 4; ++i) h4[tid + i * 256] = z;
    }
    if (tid == 0) gcount = 0;

    // ---- load row -> keys in registers ----
    unsigned key[16];
    const bool has4 = (tid < 16);
    const float4* xin = reinterpret_cast<const float4*>(x + base);
#pragma unroll
    for (int s = 0; s < 4; ++s) {
        int p = tid + s * 256;
        if (s < 3 || has4) {
            float4 f = xin[p];
            key[4*s+0] = f2k(f.x); key[4*s+1] = f2k(f.y);
            key[4*s+2] = f2k(f.z); key[4*s+3] = f2k(f.w);
        } else {
            key[4*s+0] = key[4*s+1] = key[4*s+2] = key[4*s+3] = 0u;
        }
    }
    __syncthreads();

    // ---- round 1: 12-bit digit histogram via shared atomics ----
#pragma unroll
    for (int j = 0; j < 16; ++j) {
        bool valid = (j < 12) || has4;
        if (valid) atomicAdd(&hist[key[j] >> 20], 1u);
    }
    __syncthreads();

    // ---- pick crossing bucket among 4096 (thread owns buckets 16t..16t+15) ----
    const uint4* hh = reinterpret_cast<const uint4*>(hist) + tid * 4;
    unsigned tot = 0;
#pragma unroll
    for (int q = 0; q < 4; ++q) { uint4 v = hh[q]; tot += v.x + v.y + v.z + v.w; }
    unsigned s = tot;                       // warp suffix-inclusive sum
#pragma unroll
    for (int off = 1; off <= 16; off <<= 1) {
        unsigned v = __shfl_down_sync(0xFFFFFFFFu, s, off);
        if (lane + off < 32) s += v;
    }
    if (lane == 0) warpcnt[warp] = s;       // warp total
    __syncthreads();
    unsigned above = s - tot;               // higher lanes in my warp
#pragma unroll
    for (int w = 0; w < 8; ++w) if (w > warp) above += warpcnt[w];
    {
        unsigned run = above;               // walk my 16 buckets, high -> low
#pragma unroll
        for (int q = 3; q >= 0; --q) {
            uint4 v = hh[q];
            unsigned cc[4] = { v.x, v.y, v.z, v.w };
#pragma unroll
            for (int j = 3; j >= 0; --j) {
                unsigned nr = run + cc[j];
                if (nr >= KSEL && run < KSEL) {
                    sb_d1   = (unsigned)(tid * 16 + q * 4 + j);
                    sb_rank = KSEL - run;
                    sb_m    = cc[j];
                }
                run = nr;
            }
        }
    }
    __syncthreads();
    const unsigned d1 = sb_d1;
    const unsigned m1 = sb_m;               // compacted list length

    // ---- compact bucket d1 to shared ----
    unsigned mycnt = 0;
#pragma unroll
    for (int j = 0; j < 16; ++j) {
        bool valid = (j < 12) || has4;
        mycnt += (valid && (key[j] >> 20) == d1) ? 1u : 0u;
    }
    unsigned isum = mycnt;
#pragma unroll
    for (int off = 1; off <= 16; off <<= 1) {
        unsigned v = __shfl_up_sync(0xFFFFFFFFu, isum, off);
        if (lane >= off) isum += v;
    }
    if (lane == 31) warpcnt[warp] = isum;
    __syncthreads();
    unsigned pos = isum - mycnt;
#pragma unroll
    for (int w = 0; w < 8; ++w) pos += (w < warp) ? warpcnt[w] : 0u;
#pragma unroll
    for (int j = 0; j < 16; ++j) {
        bool valid = (j < 12) || has4;
        if (valid && (key[j] >> 20) == d1) buf[pos++] = key[j];
    }
    __syncthreads();

    // ---- 4-bit rounds over static tiny list (usually 0-1 iterations) ----
    unsigned prefix = d1, rk = sb_rank, mcur = m1;
    int shift = 16;
    while (mcur > 32 && shift >= 0) {
        unsigned long long acc = 0ull;      // 16 nibble fields, per-thread elems <= 13
        int top = shift + 4;
        for (unsigned i = tid; i < m1; i += 256) {
            unsigned k = buf[i];
            if ((k >> top) == prefix) acc += 1ull << (((k >> shift) & 15u) * 4u);
        }
        {
            unsigned lo = (unsigned)acc, hi = (unsigned)(acc >> 32);
            unsigned r0 = (lo & 0x0F0F0F0Fu);
            unsigned r1 = ((lo >> 4) & 0x0F0F0F0Fu);
            unsigned r2 = (hi & 0x0F0F0F0Fu);
            unsigned r3 = ((hi >> 4) & 0x0F0F0F0Fu);
#pragma unroll
            for (int off = 1; off <= 4; off <<= 1) {
                r0 += __shfl_xor_sync(0xFFFFFFFFu, r0, off);
                r1 += __shfl_xor_sync(0xFFFFFFFFu, r1, off);
                r2 += __shfl_xor_sync(0xFFFFFFFFu, r2, off);
                r3 += __shfl_xor_sync(0xFFFFFFFFu, r3, off);
            }
            if ((lane & 7) == 0) wsum[warp][lane >> 3] = make_uint4(r0, r1, r2, r3);
        }
        __syncthreads();
        if (warp == 0) {
            unsigned cnt = 0;
            if (lane < 16) {
                int word = (lane & 1) | ((lane >> 3) << 1);
                int sh   = ((lane & 7) >> 1) * 8;
#pragma unroll
                for (int w = 0; w < 8; ++w)
#pragma unroll
                    for (int g = 0; g < 4; ++g) {
                        const unsigned* ws = reinterpret_cast<const unsigned*>(&wsum[w][g]);
                        cnt += (ws[word] >> sh) & 0xFFu;
                    }
            }
            unsigned ssum = cnt;
#pragma unroll
            for (int off = 1; off <= 8; off <<= 1) {
                unsigned v = __shfl_down_sync(0xFFFFFFFFu, ssum, off);
                if (lane + off < 16) ssum += v;
            }
            if (lane < 16 && ssum >= rk && (ssum - cnt) < rk) {
                sb_d1   = (prefix << 4) | (unsigned)lane;
                sb_rank = rk - (ssum - cnt);
                sb_m    = cnt;
            }
        }
        __syncthreads();
        prefix = sb_d1; rk = sb_rank; mcur = sb_m;
        shift -= 4;
    }

    // ---- tail: gather <=32 candidates, warp-0 ballot bisection ----
    int rem = shift + 4;
    if (rem > 0) {
        for (unsigned i = tid; i < m1; i += 256) {
            unsigned k = buf[i];
            if ((k >> rem) == prefix) {
                int p = atomicAdd(&gcount, 1);
                if (p < 32) gbuf[p] = k;
            }
        }
        __syncthreads();
        if (warp == 0) {
            int n = gcount; if (n > 32) n = 32;
            unsigned ck = (lane < n) ? gbuf[lane] : 0u;
            bool alive = (lane < n);
            unsigned r = rk;
            unsigned tk = prefix << rem;
            for (int b = rem - 1; b >= 0; --b) {
                bool bit = ((ck >> b) & 1u) != 0u;
                unsigned bal = __ballot_sync(0xFFFFFFFFu, alive && bit);
                unsigned c = __popc(bal);
                if (c >= r) { alive = alive && bit; tk |= (1u << b); }
                else        { r -= c; alive = alive && !bit; }
            }
            if (lane == 0) sb_tkey = tk;
        }
    } else {
        if (tid == 0) sb_tkey = prefix;    // all 32 bits resolved (ties)
    }
    __syncthreads();
    const unsigned tkey = sb_tkey;

    // ---- mask + store (key < tkey  <=>  x < t) ----
    float4* po = reinterpret_cast<float4*>(out + base);
#pragma unroll
    for (int s2 = 0; s2 < 4; ++s2) {
        int p = tid + s2 * 256;
        if (s2 < 3 || has4) {
            float4 o;
            o.x = (key[4*s2+0] < tkey) ? k2f(key[4*s2+0]) : 0.0f;
            o.y = (key[4*s2+1] < tkey) ? k2f(key[4*s2+1]) : 0.0f;
            o.z = (key[4*s2+2] < tkey) ? k2f(key[4*s2+2]) : 0.0f;
            o.w = (key[4*s2+3] < tkey) ? k2f(key[4*s2+3]) : 0.0f;
            po[p] = o;
        }
    }
}

extern "C" void kernel_launch(void* const* d_in, const int* in_sizes, int n_in,
                              void* d_out, int out_size) {
    const float* x = (const float*)d_in[0];
    float* out = (float*)d_out;
    int rows = in_sizes[0] / NROW;   // 16384
    wta2d_kernel<<<rows, 256>>>(x, out);
}

// round 5
// speedup vs baseline: 2.6820x; 1.2800x over previous
#include <cuda_runtime.h>
#include <cuda_bf16.h>

// WTA2D: per (B,C) row of H*W=3136 fp32, t = 313th-largest, out = (t > x) ? x : 0.
//
// One CTA (256 thr) per row, row in registers (16 keys/thread).
// Round 1: 16-bucket register-packed nibble histogram (ALU only) -> d1, ~1450 left.
// Round 2: 256-bucket shared ATOMIC histogram over bucket-d1 elems (from regs)
//          -> 12-bit prefix, ~66 left.
// Tail: gather <=64 candidates from registers, warp-0 ballot bisection over the
// remaining 20 bits (2 candidates/lane). Generic fallback (compact + 4-bit
// rounds) only if the 12-bit bucket exceeds 64 elements.

#define NROW 3136
#define KSEL 313u

__device__ __forceinline__ unsigned f2k(float f) {
    unsigned u = __float_as_uint(f);
    return (u & 0x80000000u) ? ~u : (u | 0x80000000u);
}
__device__ __forceinline__ float k2f(unsigned k) {
    unsigned u = (k & 0x80000000u) ? (k ^ 0x80000000u) : ~k;
    return __uint_as_float(u);
}

__global__ void __launch_bounds__(256, 6)
wta2d_kernel(const float* __restrict__ x, float* __restrict__ out) {
    const int tid  = threadIdx.x;
    const int lane = tid & 31;
    const int warp = tid >> 5;
    const size_t base = (size_t)blockIdx.x * NROW;

    __shared__ unsigned hist[256];         // 8-bit second-digit histogram
    __shared__ unsigned buf[NROW];         // fallback only
    __shared__ uint4 wsum[8][4];
    __shared__ unsigned warpcnt[8];
    __shared__ unsigned sb_d, sb_rank, sb_m, sb_tkey;
    __shared__ unsigned gbuf[64];
    __shared__ int gcount;

    hist[tid] = 0u;                        // blockDim == 256
    if (tid == 0) gcount = 0;

    // ---- load row -> keys in registers ----
    unsigned key[16];
    const bool has4 = (tid < 16);
    const float4* xin = reinterpret_cast<const float4*>(x + base);
#pragma unroll
    for (int s = 0; s < 4; ++s) {
        int p = tid + s * 256;
        if (s < 3 || has4) {
            float4 f = xin[p];
            key[4*s+0] = f2k(f.x); key[4*s+1] = f2k(f.y);
            key[4*s+2] = f2k(f.z); key[4*s+3] = f2k(f.w);
        } else {
            key[4*s+0] = key[4*s+1] = key[4*s+2] = key[4*s+3] = 0u;
        }
    }

    // ---- round 1: top-nibble histogram, nibble-packed (fields <= 8) ----
    unsigned long long acc0 = 0ull, acc1 = 0ull;
#pragma unroll
    for (int j = 0; j < 16; ++j) {
        unsigned s = (key[j] >> 26) & 0x3Cu;   // 4 * top_nibble
        unsigned long long inc = 1ull << s;
        bool valid = (j < 12) || has4;
        if (j < 8) acc0 += inc;
        else if (valid) acc1 += inc;
    }
    {
        unsigned lo0 = (unsigned)acc0, hi0 = (unsigned)(acc0 >> 32);
        unsigned lo1 = (unsigned)acc1, hi1 = (unsigned)(acc1 >> 32);
        unsigned r0 = (lo0 & 0x0F0F0F0Fu)        + (lo1 & 0x0F0F0F0Fu);
        unsigned r1 = ((lo0 >> 4) & 0x0F0F0F0Fu) + ((lo1 >> 4) & 0x0F0F0F0Fu);
        unsigned r2 = (hi0 & 0x0F0F0F0Fu)        + (hi1 & 0x0F0F0F0Fu);
        unsigned r3 = ((hi0 >> 4) & 0x0F0F0F0Fu) + ((hi1 >> 4) & 0x0F0F0F0Fu);
#pragma unroll
        for (int off = 1; off <= 4; off <<= 1) {
            r0 += __shfl_xor_sync(0xFFFFFFFFu, r0, off);
            r1 += __shfl_xor_sync(0xFFFFFFFFu, r1, off);
            r2 += __shfl_xor_sync(0xFFFFFFFFu, r2, off);
            r3 += __shfl_xor_sync(0xFFFFFFFFu, r3, off);
        }
        if ((lane & 7) == 0) wsum[warp][lane >> 3] = make_uint4(r0, r1, r2, r3);
    }
    __syncthreads();

    if (warp == 0) {    // combine, suffix-scan 16 buckets, pick d1
        unsigned cnt = 0;
        if (lane < 16) {
            int word = (lane & 1) | ((lane >> 3) << 1);
            int sh   = ((lane & 7) >> 1) * 8;
#pragma unroll
            for (int w = 0; w < 8; ++w)
#pragma unroll
                for (int g = 0; g < 4; ++g) {
                    const unsigned* ws = reinterpret_cast<const unsigned*>(&wsum[w][g]);
                    cnt += (ws[word] >> sh) & 0xFFu;
                }
        }
        unsigned ssum = cnt;
#pragma unroll
        for (int off = 1; off <= 8; off <<= 1) {
            unsigned v = __shfl_down_sync(0xFFFFFFFFu, ssum, off);
            if (lane + off < 16) ssum += v;
        }
        if (lane < 16 && ssum >= KSEL && (ssum - cnt) < KSEL) {
            sb_d    = (unsigned)lane;
            sb_rank = KSEL - (ssum - cnt);
        }
    }
    __syncthreads();
    const unsigned d1 = sb_d;

    // ---- round 2: 8-bit histogram over bucket-d1 elems (shared atomics) ----
#pragma unroll
    for (int j = 0; j < 16; ++j) {
        bool valid = (j < 12) || has4;
        if (valid && (key[j] >> 28) == d1)
            atomicAdd(&hist[(key[j] >> 20) & 0xFFu], 1u);
    }
    __syncthreads();

    if (warp == 0) {    // pick among 256 buckets: lane owns 8 (hist[lane*8..])
        unsigned rk1 = sb_rank;
        __syncwarp();
        const uint4* h4 = reinterpret_cast<const uint4*>(hist) + lane * 2;
        uint4 v0 = h4[0], v1 = h4[1];
        unsigned cc[8] = { v0.x, v0.y, v0.z, v0.w, v1.x, v1.y, v1.z, v1.w };
        unsigned tot = cc[0]+cc[1]+cc[2]+cc[3]+cc[4]+cc[5]+cc[6]+cc[7];
        unsigned s = tot;
#pragma unroll
        for (int off = 1; off <= 16; off <<= 1) {
            unsigned v = __shfl_down_sync(0xFFFFFFFFu, s, off);
            if (lane + off < 32) s += v;
        }
        unsigned run = s - tot;            // total in higher lanes' buckets
#pragma unroll
        for (int j = 7; j >= 0; --j) {
            unsigned nr = run + cc[j];
            if (nr >= rk1 && run < rk1) {
                sb_d    = (d1 << 8) | (unsigned)(lane * 8 + j);
                sb_rank = rk1 - run;
                sb_m    = cc[j];
            }
            run = nr;
        }
    }
    __syncthreads();
    const unsigned prefix12 = sb_d;        // key >> 20 == prefix12
    const unsigned rk2 = sb_rank;
    const unsigned m2  = sb_m;

    if (m2 <= 64u) {
        // ---- fast tail: gather from registers, bisect 20 bits ----
#pragma unroll
        for (int j = 0; j < 16; ++j) {
            bool valid = (j < 12) || has4;
            if (valid && (key[j] >> 20) == prefix12)
                gbuf[atomicAdd(&gcount, 1)] = key[j];
        }
        __syncthreads();
        if (warp == 0) {
            int n = gcount;
            unsigned ck0 = (lane      < n) ? gbuf[lane]      : 0u;
            unsigned ck1 = (lane + 32 < n) ? gbuf[lane + 32] : 0u;
            bool a0 = (lane < n), a1 = (lane + 32 < n);
            unsigned r = rk2;
            unsigned tk = prefix12 << 20;
#pragma unroll
            for (int b = 19; b >= 0; --b) {
                bool bit0 = ((ck0 >> b) & 1u) != 0u;
                bool bit1 = ((ck1 >> b) & 1u) != 0u;
                unsigned c = __popc(__ballot_sync(0xFFFFFFFFu, a0 && bit0))
                           + __popc(__ballot_sync(0xFFFFFFFFu, a1 && bit1));
                if (c >= r) { a0 = a0 && bit0; a1 = a1 && bit1; tk |= (1u << b); }
                else        { r -= c; a0 = a0 && !bit0; a1 = a1 && !bit1; }
            }
            if (lane == 0) sb_tkey = tk;
        }
        __syncthreads();
    } else {
        // ---- generic fallback: compact prefix12 bucket, 4-bit rounds ----
        unsigned mycnt = 0;
#pragma unroll
        for (int j = 0; j < 16; ++j) {
            bool valid = (j < 12) || has4;
            mycnt += (valid && (key[j] >> 20) == prefix12) ? 1u : 0u;
        }
        unsigned isum = mycnt;
#pragma unroll
        for (int off = 1; off <= 16; off <<= 1) {
            unsigned v = __shfl_up_sync(0xFFFFFFFFu, isum, off);
            if (lane >= off) isum += v;
        }
        if (lane == 31) warpcnt[warp] = isum;
        __syncthreads();
        unsigned pos = isum - mycnt;
#pragma unroll
        for (int w = 0; w < 8; ++w) pos += (w < warp) ? warpcnt[w] : 0u;
#pragma unroll
        for (int j = 0; j < 16; ++j) {
            bool valid = (j < 12) || has4;
            if (valid && (key[j] >> 20) == prefix12) buf[pos++] = key[j];
        }
        __syncthreads();

        unsigned prefix = prefix12, rk = rk2, mcur = m2;
        int shift = 16;
        while (mcur > 32 && shift >= 0) {
            unsigned long long acc = 0ull;
            int top = shift + 4;
            for (unsigned i = tid; i < m2; i += 256) {
                unsigned k = buf[i];
                if ((k >> top) == prefix) acc += 1ull << (((k >> shift) & 15u) * 4u);
            }
            {
                unsigned lo = (unsigned)acc, hi = (unsigned)(acc >> 32);
                unsigned r0 = (lo & 0x0F0F0F0Fu);
                unsigned r1 = ((lo >> 4) & 0x0F0F0F0Fu);
                unsigned r2 = (hi & 0x0F0F0F0Fu);
                unsigned r3 = ((hi >> 4) & 0x0F0F0F0Fu);
#pragma unroll
                for (int off = 1; off <= 4; off <<= 1) {
                    r0 += __shfl_xor_sync(0xFFFFFFFFu, r0, off);
                    r1 += __shfl_xor_sync(0xFFFFFFFFu, r1, off);
                    r2 += __shfl_xor_sync(0xFFFFFFFFu, r2, off);
                    r3 += __shfl_xor_sync(0xFFFFFFFFu, r3, off);
                }
                if ((lane & 7) == 0) wsum[warp][lane >> 3] = make_uint4(r0, r1, r2, r3);
            }
            __syncthreads();
            if (warp == 0) {
                unsigned cnt = 0;
                if (lane < 16) {
                    int word = (lane & 1) | ((lane >> 3) << 1);
                    int sh   = ((lane & 7) >> 1) * 8;
#pragma unroll
                    for (int w = 0; w < 8; ++w)
#pragma unroll
                        for (int g = 0; g < 4; ++g) {
                            const unsigned* ws = reinterpret_cast<const unsigned*>(&wsum[w][g]);
                            cnt += (ws[word] >> sh) & 0xFFu;
                        }
                }
                unsigned ssum = cnt;
#pragma unroll
                for (int off = 1; off <= 8; off <<= 1) {
                    unsigned v = __shfl_down_sync(0xFFFFFFFFu, ssum, off);
                    if (lane + off < 16) ssum += v;
                }
                if (lane < 16 && ssum >= rk && (ssum - cnt) < rk) {
                    sb_d    = (prefix << 4) | (unsigned)lane;
                    sb_rank = rk - (ssum - cnt);
                    sb_m    = cnt;
                }
            }
            __syncthreads();
            prefix = sb_d; rk = sb_rank; mcur = sb_m;
            shift -= 4;
        }

        int rem = shift + 4;
        if (rem > 0) {
            if (tid == 0) gcount = 0;
            __syncthreads();
            for (unsigned i = tid; i < m2; i += 256) {
                unsigned k = buf[i];
                if ((k >> rem) == prefix) {
                    int p = atomicAdd(&gcount, 1);
                    if (p < 32) gbuf[p] = k;
                }
            }
            __syncthreads();
            if (warp == 0) {
                int n = gcount; if (n > 32) n = 32;
                unsigned ck = (lane < n) ? gbuf[lane] : 0u;
                bool alive = (lane < n);
                unsigned r = rk;
                unsigned tk = prefix << rem;
                for (int b = rem - 1; b >= 0; --b) {
                    bool bit = ((ck >> b) & 1u) != 0u;
                    unsigned bal = __ballot_sync(0xFFFFFFFFu, alive && bit);
                    unsigned c = __popc(bal);
                    if (c >= r) { alive = alive && bit; tk |= (1u << b); }
                    else        { r -= c; alive = alive && !bit; }
                }
                if (lane == 0) sb_tkey = tk;
            }
        } else {
            if (tid == 0) sb_tkey = prefix;
        }
        __syncthreads();
    }
    const unsigned tkey = sb_tkey;

    // ---- mask + store (key < tkey  <=>  x < t) ----
    float4* po = reinterpret_cast<float4*>(out + base);
#pragma unroll
    for (int s2 = 0; s2 < 4; ++s2) {
        int p = tid + s2 * 256;
        if (s2 < 3 || has4) {
            float4 o;
            o.x = (key[4*s2+0] < tkey) ? k2f(key[4*s2+0]) : 0.0f;
            o.y = (key[4*s2+1] < tkey) ? k2f(key[4*s2+1]) : 0.0f;
            o.z = (key[4*s2+2] < tkey) ? k2f(key[4*s2+2]) : 0.0f;
            o.w = (key[4*s2+3] < tkey) ? k2f(key[4*s2+3]) : 0.0f;
            po[p] = o;
        }
    }
}

extern "C" void kernel_launch(void* const* d_in, const int* in_sizes, int n_in,
                              void* d_out, int out_size) {
    const float* x = (const float*)d_in[0];
    float* out = (float*)d_out;
    int rows = in_sizes[0] / NROW;   // 16384
    wta2d_kernel<<<rows, 256>>>(x, out);
}

// round 6
// speedup vs baseline: 3.7086x; 1.3828x over previous
#include <cuda_runtime.h>
#include <cuda_bf16.h>

// WTA2D: per (B,C) row of H*W=3136 fp32, t = 313th-largest, out = (t > x) ? x : 0.
//
// One CTA (256 thr) per row, row in registers (16 keys/thread).
// Round 1: 256-bucket shared ATOMIC histogram of top byte (all elems).
// Round 2: 256-bucket shared ATOMIC histogram of 2nd byte over winning bucket.
// -> 16-bit prefix resolved, bucket typically ~10-40 elems.
// Tail: gather <=64 candidates from registers, warp-0 ballot bisection over the
// remaining 16 bits (2 candidates/lane). Generic fallback (compact + 4-bit
// rounds) if the 16-bit bucket exceeds 64 elements.

#define NROW 3136
#define KSEL 313u

__device__ __forceinline__ unsigned f2k(float f) {
    unsigned u = __float_as_uint(f);
    return (u & 0x80000000u) ? ~u : (u | 0x80000000u);
}
__device__ __forceinline__ float k2f(unsigned k) {
    unsigned u = (k & 0x80000000u) ? (k ^ 0x80000000u) : ~k;
    return __uint_as_float(u);
}

__global__ void __launch_bounds__(256, 6)
wta2d_kernel(const float* __restrict__ x, float* __restrict__ out) {
    const int tid  = threadIdx.x;
    const int lane = tid & 31;
    const int warp = tid >> 5;
    const size_t base = (size_t)blockIdx.x * NROW;

    __shared__ unsigned histA[256];
    __shared__ unsigned histB[256];
    __shared__ unsigned buf[NROW];          // fallback only
    __shared__ uint4 wsum[8][4];            // fallback only
    __shared__ unsigned warpcnt[8];         // fallback only
    __shared__ unsigned sb_d, sb_rank, sb_m, sb_tkey;
    __shared__ unsigned gbuf[64];
    __shared__ int gcount;

    histA[tid] = 0u;                        // blockDim == 256
    histB[tid] = 0u;
    if (tid == 0) gcount = 0;

    // ---- load row -> keys in registers ----
    unsigned key[16];
    const bool has4 = (tid < 16);
    const float4* xin = reinterpret_cast<const float4*>(x + base);
#pragma unroll
    for (int s = 0; s < 4; ++s) {
        int p = tid + s * 256;
        if (s < 3 || has4) {
            float4 f = xin[p];
            key[4*s+0] = f2k(f.x); key[4*s+1] = f2k(f.y);
            key[4*s+2] = f2k(f.z); key[4*s+3] = f2k(f.w);
        } else {
            key[4*s+0] = key[4*s+1] = key[4*s+2] = key[4*s+3] = 0u;
        }
    }
    __syncthreads();                        // hist zeros visible

    // ---- round 1: top-byte histogram (shared atomics) ----
#pragma unroll
    for (int j = 0; j < 16; ++j) {
        bool valid = (j < 12) || has4;
        if (valid) atomicAdd(&histA[key[j] >> 24], 1u);
    }
    __syncthreads();

    if (warp == 0) {    // pick among 256: lane owns histA[lane*8 .. lane*8+7]
        const uint4* h4 = reinterpret_cast<const uint4*>(histA) + lane * 2;
        uint4 v0 = h4[0], v1 = h4[1];
        unsigned cc[8] = { v0.x, v0.y, v0.z, v0.w, v1.x, v1.y, v1.z, v1.w };
        unsigned tot = cc[0]+cc[1]+cc[2]+cc[3]+cc[4]+cc[5]+cc[6]+cc[7];
        unsigned s = tot;
#pragma unroll
        for (int off = 1; off <= 16; off <<= 1) {
            unsigned v = __shfl_down_sync(0xFFFFFFFFu, s, off);
            if (lane + off < 32) s += v;
        }
        unsigned run = s - tot;             // total in higher buckets
#pragma unroll
        for (int j = 7; j >= 0; --j) {
            unsigned nr = run + cc[j];
            if (nr >= KSEL && run < KSEL) {
                sb_d    = (unsigned)(lane * 8 + j);
                sb_rank = KSEL - run;
            }
            run = nr;
        }
    }
    __syncthreads();
    const unsigned d8 = sb_d;

    // ---- round 2: 2nd-byte histogram over bucket-d8 elems ----
#pragma unroll
    for (int j = 0; j < 16; ++j) {
        bool valid = (j < 12) || has4;
        if (valid && (key[j] >> 24) == d8)
            atomicAdd(&histB[(key[j] >> 16) & 0xFFu], 1u);
    }
    __syncthreads();

    if (warp == 0) {    // pick among 256 again
        unsigned rk1 = sb_rank;
        __syncwarp();
        const uint4* h4 = reinterpret_cast<const uint4*>(histB) + lane * 2;
        uint4 v0 = h4[0], v1 = h4[1];
        unsigned cc[8] = { v0.x, v0.y, v0.z, v0.w, v1.x, v1.y, v1.z, v1.w };
        unsigned tot = cc[0]+cc[1]+cc[2]+cc[3]+cc[4]+cc[5]+cc[6]+cc[7];
        unsigned s = tot;
#pragma unroll
        for (int off = 1; off <= 16; off <<= 1) {
            unsigned v = __shfl_down_sync(0xFFFFFFFFu, s, off);
            if (lane + off < 32) s += v;
        }
        unsigned run = s - tot;
#pragma unroll
        for (int j = 7; j >= 0; --j) {
            unsigned nr = run + cc[j];
            if (nr >= rk1 && run < rk1) {
                sb_d    = (d8 << 8) | (unsigned)(lane * 8 + j);
                sb_rank = rk1 - run;
                sb_m    = cc[j];
            }
            run = nr;
        }
    }
    __syncthreads();
    const unsigned prefix16 = sb_d;         // key >> 16 == prefix16
    const unsigned rk2 = sb_rank;
    const unsigned m2  = sb_m;

    if (m2 <= 64u) {
        // ---- fast tail: gather from registers, bisect low 16 bits ----
#pragma unroll
        for (int j = 0; j < 16; ++j) {
            bool valid = (j < 12) || has4;
            if (valid && (key[j] >> 16) == prefix16)
                gbuf[atomicAdd(&gcount, 1)] = key[j];
        }
        __syncthreads();
        if (warp == 0) {
            int n = gcount;
            unsigned ck0 = (lane      < n) ? gbuf[lane]      : 0u;
            unsigned ck1 = (lane + 32 < n) ? gbuf[lane + 32] : 0u;
            bool a0 = (lane < n), a1 = (lane + 32 < n);
            unsigned r = rk2;
            unsigned tk = prefix16 << 16;
#pragma unroll
            for (int b = 15; b >= 0; --b) {
                bool bit0 = ((ck0 >> b) & 1u) != 0u;
                bool bit1 = ((ck1 >> b) & 1u) != 0u;
                unsigned c = __popc(__ballot_sync(0xFFFFFFFFu, a0 && bit0))
                           + __popc(__ballot_sync(0xFFFFFFFFu, a1 && bit1));
                if (c >= r) { a0 = a0 && bit0; a1 = a1 && bit1; tk |= (1u << b); }
                else        { r -= c; a0 = a0 && !bit0; a1 = a1 && !bit1; }
            }
            if (lane == 0) sb_tkey = tk;
        }
        __syncthreads();
    } else {
        // ---- generic fallback: compact prefix16 bucket, 4-bit rounds ----
        unsigned mycnt = 0;
#pragma unroll
        for (int j = 0; j < 16; ++j) {
            bool valid = (j < 12) || has4;
            mycnt += (valid && (key[j] >> 16) == prefix16) ? 1u : 0u;
        }
        unsigned isum = mycnt;
#pragma unroll
        for (int off = 1; off <= 16; off <<= 1) {
            unsigned v = __shfl_up_sync(0xFFFFFFFFu, isum, off);
            if (lane >= off) isum += v;
        }
        if (lane == 31) warpcnt[warp] = isum;
        __syncthreads();
        unsigned pos = isum - mycnt;
#pragma unroll
        for (int w = 0; w < 8; ++w) pos += (w < warp) ? warpcnt[w] : 0u;
#pragma unroll
        for (int j = 0; j < 16; ++j) {
            bool valid = (j < 12) || has4;
            if (valid && (key[j] >> 16) == prefix16) buf[pos++] = key[j];
        }
        __syncthreads();

        unsigned prefix = prefix16, rk = rk2, mcur = m2;
        int shift = 12;
        while (mcur > 32 && shift >= 0) {
            unsigned long long acc = 0ull;
            int top = shift + 4;
            for (unsigned i = tid; i < m2; i += 256) {
                unsigned k = buf[i];
                if ((k >> top) == prefix) acc += 1ull << (((k >> shift) & 15u) * 4u);
            }
            {
                unsigned lo = (unsigned)acc, hi = (unsigned)(acc >> 32);
                unsigned r0 = (lo & 0x0F0F0F0Fu);
                unsigned r1 = ((lo >> 4) & 0x0F0F0F0Fu);
                unsigned r2 = (hi & 0x0F0F0F0Fu);
                unsigned r3 = ((hi >> 4) & 0x0F0F0F0Fu);
#pragma unroll
                for (int off = 1; off <= 4; off <<= 1) {
                    r0 += __shfl_xor_sync(0xFFFFFFFFu, r0, off);
                    r1 += __shfl_xor_sync(0xFFFFFFFFu, r1, off);
                    r2 += __shfl_xor_sync(0xFFFFFFFFu, r2, off);
                    r3 += __shfl_xor_sync(0xFFFFFFFFu, r3, off);
                }
                if ((lane & 7) == 0) wsum[warp][lane >> 3] = make_uint4(r0, r1, r2, r3);
            }
            __syncthreads();
            if (warp == 0) {
                unsigned cnt = 0;
                if (lane < 16) {
                    int word = (lane & 1) | ((lane >> 3) << 1);
                    int sh   = ((lane & 7) >> 1) * 8;
#pragma unroll
                    for (int w = 0; w < 8; ++w)
#pragma unroll
                        for (int g = 0; g < 4; ++g) {
                            const unsigned* ws = reinterpret_cast<const unsigned*>(&wsum[w][g]);
                            cnt += (ws[word] >> sh) & 0xFFu;
                        }
                }
                unsigned ssum = cnt;
#pragma unroll
                for (int off = 1; off <= 8; off <<= 1) {
                    unsigned v = __shfl_down_sync(0xFFFFFFFFu, ssum, off);
                    if (lane + off < 16) ssum += v;
                }
                if (lane < 16 && ssum >= rk && (ssum - cnt) < rk) {
                    sb_d    = (prefix << 4) | (unsigned)lane;
                    sb_rank = rk - (ssum - cnt);
                    sb_m    = cnt;
                }
            }
            __syncthreads();
            prefix = sb_d; rk = sb_rank; mcur = sb_m;
            shift -= 4;
        }

        int rem = shift + 4;
        if (rem > 0) {
            if (tid == 0) gcount = 0;
            __syncthreads();
            for (unsigned i = tid; i < m2; i += 256) {
                unsigned k = buf[i];
                if ((k >> rem) == prefix) {
                    int p = atomicAdd(&gcount, 1);
                    if (p < 32) gbuf[p] = k;
                }
            }
            __syncthreads();
            if (warp == 0) {
                int n = gcount; if (n > 32) n = 32;
                unsigned ck = (lane < n) ? gbuf[lane] : 0u;
                bool alive = (lane < n);
                unsigned r = rk;
                unsigned tk = prefix << rem;
                for (int b = rem - 1; b >= 0; --b) {
                    bool bit = ((ck >> b) & 1u) != 0u;
                    unsigned bal = __ballot_sync(0xFFFFFFFFu, alive && bit);
                    unsigned c = __popc(bal);
                    if (c >= r) { alive = alive && bit; tk |= (1u << b); }
                    else        { r -= c; alive = alive && !bit; }
                }
                if (lane == 0) sb_tkey = tk;
            }
        } else {
            if (tid == 0) sb_tkey = prefix;
        }
        __syncthreads();
    }
    const unsigned tkey = sb_tkey;

    // ---- mask + store (key < tkey  <=>  x < t) ----
    float4* po = reinterpret_cast<float4*>(out + base);
#pragma unroll
    for (int s2 = 0; s2 < 4; ++s2) {
        int p = tid + s2 * 256;
        if (s2 < 3 || has4) {
            float4 o;
            o.x = (key[4*s2+0] < tkey) ? k2f(key[4*s2+0]) : 0.0f;
            o.y = (key[4*s2+1] < tkey) ? k2f(key[4*s2+1]) : 0.0f;
            o.z = (key[4*s2+2] < tkey) ? k2f(key[4*s2+2]) : 0.0f;
            o.w = (key[4*s2+3] < tkey) ? k2f(key[4*s2+3]) : 0.0f;
            po[p] = o;
        }
    }
}

extern "C" void kernel_launch(void* const* d_in, const int* in_sizes, int n_in,
                              void* d_out, int out_size) {
    const float* x = (const float*)d_in[0];
    float* out = (float*)d_out;
    int rows = in_sizes[0] / NROW;   // 16384
    wta2d_kernel<<<rows, 256>>>(x, out);
}